// round 9
// baseline (speedup 1.0000x reference)
#include <cuda_runtime.h>
#include <cstdint>

// SSIM over two [16,1,1024,1024] fp32 images, 11x11 Gaussian (sigma=1.5).
// Separable conv, packed f32x2 math. Horizontal pass reads DIRECTLY from
// global (L1-cached, halo 1.72x) -> no input smem stage, one barrier only,
// smem 28KB -> 8 CTAs/SM.

#define IMG_H 1024
#define IMG_W 1024
#define IMG_B 16
#define TS    32          // output tile 32x32
#define EHT   42          // extended tile (halo 5 each side)
#define C1V   1.0e-4f
#define C2V   9.0e-4f
#define NBLK  (IMG_B * (IMG_H / TS) * (IMG_W / TS))   // 16384

__device__ double   g_accum = 0.0;
__device__ unsigned g_count = 0;

// ---- packed f32x2 helpers (sm_103a) ----
__device__ __forceinline__ void fma2(uint64_t& acc, uint64_t a, uint64_t w) {
    asm("fma.rn.f32x2 %0, %1, %2, %0;" : "+l"(acc) : "l"(a), "l"(w));
}
__device__ __forceinline__ uint64_t mul2(uint64_t a, uint64_t b) {
    uint64_t d; asm("mul.rn.f32x2 %0, %1, %2;" : "=l"(d) : "l"(a), "l"(b));
    return d;
}
__device__ __forceinline__ uint64_t pk2(float lo, float hi) {
    uint64_t r; asm("mov.b64 %0, {%1, %2};" : "=l"(r) : "f"(lo), "f"(hi));
    return r;
}
__device__ __forceinline__ void upk(uint64_t v, float& lo, float& hi) {
    asm("mov.b64 {%0, %1}, %2;" : "=f"(lo), "=f"(hi) : "l"(v));
}
// compile-time packed weight constants (folded by ptxas)
#define WPAIR(w)      ((((uint64_t)__float_as_uint(w)) << 32) | (uint64_t)__float_as_uint(w))
#define WPAIR2(lo,hi) ((((uint64_t)__float_as_uint(hi)) << 32) | (uint64_t)__float_as_uint(lo))

// 1-D normalized gaussian, size=11, sigma=1.5
__device__ constexpr float GW[11] = {
    0.001028380f, 0.007598759f, 0.036000771f, 0.109360691f, 0.213005537f,
    0.266011721f,
    0.213005537f, 0.109360691f, 0.036000771f, 0.007598759f, 0.001028380f
};
__device__ constexpr float WZ(int i) {
    return (i >= 0 && i < 11) ? GW[i] : 0.0f;
}

__global__ __launch_bounds__(256, 8)
void ssim_main_kernel(const float* __restrict__ img1,
                      const float* __restrict__ img2,
                      float* __restrict__ out)
{
    __shared__ float2 hA[EHT][33];     // (hx,hy)   11.1 KB (col-swizzled)
    __shared__ float2 hB[EHT][33];     // (hxx,hyy) 11.1 KB (col-swizzled)
    __shared__ float  hC[EHT][35];     //  hxy       5.9 KB (stride 3 mod 4)
    __shared__ float  wsums[8];

    const int tx  = threadIdx.x;          // 0..31
    const int ty  = threadIdx.y;          // 0..7
    const int tid = ty * 32 + tx;

    const int base_row = blockIdx.y * TS - 5;
    const int base_col = blockIdx.x * TS - 5;
    const size_t ibase = (size_t)blockIdx.z * (IMG_H * IMG_W);

    // ---- Horizontal pass: 42 rows x 8 groups of 4 output cols,
    //      reading inputs straight from global (L1-resident halo) ----
    for (int p = tid; p < EHT * 8; p += 256) {
        const int row = p >> 3;
        const int c0  = (p & 7) * 4;
        const int swz = (c0 & 16) >> 3;          // 0 or 2: store swizzle
        const int gr  = base_row + row;
        const bool rok = (unsigned)gr < IMG_H;
        const float* p1 = img1 + ibase + (size_t)gr * IMG_W;
        const float* p2 = img2 + ibase + (size_t)gr * IMG_W;
        const int gc0 = base_col + c0;

        uint64_t aA[4] = {0ull,0ull,0ull,0ull};  // (hx, hy)
        uint64_t aB[4] = {0ull,0ull,0ull,0ull};  // (hxx, hyy)
        uint64_t aC[2] = {0ull,0ull};            // (hxy0,hxy1),(hxy2,hxy3)
        #pragma unroll
        for (int k = 0; k < 14; k++) {
            const int gc  = gc0 + k;
            const bool ok = rok && ((unsigned)gc < IMG_W);
            const float xv = ok ? __ldg(p1 + gc) : 0.0f;
            const float yv = ok ? __ldg(p2 + gc) : 0.0f;
            const uint64_t v   = pk2(xv, yv);
            const uint64_t v2  = mul2(v, v);
            const float    xy  = xv * yv;
            const uint64_t xyp = pk2(xy, xy);
            #pragma unroll
            for (int o = 0; o < 4; o++) {
                const int kk = k - o;
                if (kk >= 0 && kk < 11) {
                    fma2(aA[o], v,  WPAIR(GW[kk]));
                    fma2(aB[o], v2, WPAIR(GW[kk]));
                }
            }
            if (k <= 11) fma2(aC[0], xyp, WPAIR2(WZ(k),     WZ(k - 1)));
            if (k >= 2)  fma2(aC[1], xyp, WPAIR2(WZ(k - 2), WZ(k - 3)));
        }
        #pragma unroll
        for (int o = 0; o < 4; o++) {
            *(uint64_t*)&hA[row][c0 + (o ^ swz)] = aA[o];
            *(uint64_t*)&hB[row][c0 + (o ^ swz)] = aB[o];
        }
        float cv0, cv1, cv2, cv3;
        upk(aC[0], cv0, cv1);
        upk(aC[1], cv2, cv3);
        hC[row][c0 + 0] = cv0;
        hC[row][c0 + 1] = cv1;
        hC[row][c0 + 2] = cv2;
        hC[row][c0 + 3] = cv3;
    }
    __syncthreads();

    // ---- Vertical pass: thread = column tx, rows [ty*4, ty*4+4) ----
    const int txs = tx ^ ((tx & 16) >> 3);       // read-side swizzle
    uint64_t accA[4] = {0ull,0ull,0ull,0ull};
    uint64_t accB[4] = {0ull,0ull,0ull,0ull};
    uint64_t accC[2] = {0ull,0ull};
    const int r0 = ty * 4;
    #pragma unroll
    for (int k = 0; k < 14; k++) {
        const uint64_t a = *(const uint64_t*)&hA[r0 + k][txs];
        const uint64_t b = *(const uint64_t*)&hB[r0 + k][txs];
        const float    c = hC[r0 + k][tx];
        const uint64_t cp = pk2(c, c);
        #pragma unroll
        for (int o = 0; o < 4; o++) {
            const int kk = k - o;
            if (kk >= 0 && kk < 11) {
                fma2(accA[o], a, WPAIR(GW[kk]));
                fma2(accB[o], b, WPAIR(GW[kk]));
            }
        }
        if (k <= 11) fma2(accC[0], cp, WPAIR2(WZ(k),     WZ(k - 1)));
        if (k >= 2)  fma2(accC[1], cp, WPAIR2(WZ(k - 2), WZ(k - 3)));
    }

    // ---- SSIM per pixel + local sum ----
    float exyv[4];
    upk(accC[0], exyv[0], exyv[1]);
    upk(accC[1], exyv[2], exyv[3]);
    float lsum = 0.0f;
    #pragma unroll
    for (int o = 0; o < 4; o++) {
        float mux, muy, ex2, ey2;
        upk(accA[o], mux, muy);
        upk(accB[o], ex2, ey2);
        const float exy = exyv[o];
        const float mx2 = mux * mux;
        const float my2 = muy * muy;
        const float mxy = mux * muy;
        const float sx2 = ex2 - mx2;
        const float sy2 = ey2 - my2;
        const float sxy = exy - mxy;
        const float num = (2.0f * mxy + C1V) * (2.0f * sxy + C2V);
        const float den = (mx2 + my2 + C1V) * (sx2 + sy2 + C2V);
        lsum += __fdividef(num, den);
    }

    // ---- Reduce: warp shuffle -> block -> global atomic ----
    #pragma unroll
    for (int off = 16; off > 0; off >>= 1)
        lsum += __shfl_xor_sync(0xffffffffu, lsum, off);
    if (tx == 0) wsums[ty] = lsum;
    __syncthreads();

    if (tid == 0) {
        float s = 0.0f;
        #pragma unroll
        for (int i = 0; i < 8; i++) s += wsums[i];
        atomicAdd(&g_accum, (double)s);
        __threadfence();
        const unsigned t = atomicAdd(&g_count, 1u);
        if (t == (unsigned)(NBLK - 1)) {
            const double tot = *((volatile double*)&g_accum);
            out[0] = (float)(tot / 16777216.0);
            // reset state for the next graph replay
            *((volatile double*)&g_accum) = 0.0;
            __threadfence();
            *((volatile unsigned*)&g_count) = 0u;
        }
    }
}

extern "C" void kernel_launch(void* const* d_in, const int* in_sizes, int n_in,
                              void* d_out, int out_size)
{
    const float* img1 = (const float*)d_in[0];
    const float* img2 = (const float*)d_in[1];
    // d_in[2] (11x11 gaussian) unused: separable weights are hardcoded.
    float* out = (float*)d_out;

    dim3 grid(IMG_W / TS, IMG_H / TS, IMG_B);
    dim3 block(32, 8);
    ssim_main_kernel<<<grid, block>>>(img1, img2, out);
}